// round 1
// baseline (speedup 1.0000x reference)
#include <cuda_runtime.h>
#include <cuda_bf16.h>
#include <math.h>

#define NMAX 100000
#define EMAX 1600000
#define HID 64

// ---------------- scratch (static device globals; no allocation) ----------------
__device__ int   g_deg[NMAX];
__device__ int   g_rowptr[NMAX + 1];
__device__ int   g_fill[NMAX];
__device__ int   g_bsums[256];
__device__ float g_inv[NMAX];
__device__ int   g_col[EMAX];
__device__ float g_mean[(size_t)NMAX * HID];
__device__ float g_h1[(size_t)NMAX * HID];
__device__ float g_h2[(size_t)NMAX * HID];
__device__ int   g_is64;

// ---------------- dtype detection for edge_index (int64 vs int32) ----------------
__global__ void k_detect(const unsigned int* __restrict__ p) {
    if (threadIdx.x == 0 && blockIdx.x == 0) {
        int ok = 1;
        #pragma unroll
        for (int i = 0; i < 64; i++)
            if (p[2 * i + 1] != 0u) ok = 0;
        g_is64 = ok;
    }
}

__device__ __forceinline__ int load_idx(const void* base, long long i, int is64) {
    if (is64) return (int)((const long long*)base)[i];
    return ((const int*)base)[i];
}

// ---------------- CSR build ----------------
__global__ void k_zero(int* __restrict__ deg, int n) {
    int i = blockIdx.x * blockDim.x + threadIdx.x;
    if (i < n) deg[i] = 0;
}

__global__ void k_count(const void* __restrict__ ei, int* __restrict__ deg, int e) {
    int i = blockIdx.x * blockDim.x + threadIdx.x;
    int is64 = g_is64;
    if (i < e) {
        int d = load_idx(ei, (long long)e + i, is64); // dst row
        atomicAdd(&deg[d], 1);
    }
}

// block-wise exclusive scan (1024 elements / block)
__global__ void k_scan1(const int* __restrict__ deg, int* __restrict__ rowptr,
                        int* __restrict__ bsums, int n) {
    __shared__ int warp_tot[32];
    int i = blockIdx.x * 1024 + threadIdx.x;
    int lane = threadIdx.x & 31, wid = threadIdx.x >> 5;
    int v = (i < n) ? deg[i] : 0;
    int x = v;
    #pragma unroll
    for (int d = 1; d < 32; d <<= 1) {
        int y = __shfl_up_sync(0xffffffffu, x, d);
        if (lane >= d) x += y;
    }
    if (lane == 31) warp_tot[wid] = x;
    __syncthreads();
    if (wid == 0) {
        int t = warp_tot[lane];
        #pragma unroll
        for (int d = 1; d < 32; d <<= 1) {
            int y = __shfl_up_sync(0xffffffffu, t, d);
            if (lane >= d) t += y;
        }
        warp_tot[lane] = t;
    }
    __syncthreads();
    int base = (wid > 0) ? warp_tot[wid - 1] : 0;
    if (i < n) rowptr[i] = base + x - v;           // exclusive within block
    if (threadIdx.x == 0) bsums[blockIdx.x] = warp_tot[31];
}

__global__ void k_scan2(int* __restrict__ bsums, int nb) {
    if (threadIdx.x == 0 && blockIdx.x == 0) {
        int acc = 0;
        for (int b = 0; b < nb; b++) { int t = bsums[b]; bsums[b] = acc; acc += t; }
    }
}

__global__ void k_scan3(int* __restrict__ rowptr, const int* __restrict__ bsums,
                        const int* __restrict__ deg, int* __restrict__ fill,
                        float* __restrict__ inv, int n, int e) {
    int i = blockIdx.x * blockDim.x + threadIdx.x;
    if (i < n) {
        int rp = rowptr[i] + bsums[i >> 10];
        rowptr[i] = rp;
        fill[i] = rp;
        int d = deg[i];
        inv[i] = 1.0f / (float)max(d, 1);
    }
    if (i == 0) rowptr[n] = e;
}

__global__ void k_scatter(const void* __restrict__ ei, int* __restrict__ fill,
                          int* __restrict__ col, int e) {
    int i = blockIdx.x * blockDim.x + threadIdx.x;
    int is64 = g_is64;
    if (i < e) {
        int d = load_idx(ei, (long long)e + i, is64);
        int s = load_idx(ei, (long long)i, is64);
        int p = atomicAdd(&fill[d], 1);
        col[p] = s;
    }
}

// ---------------- mean aggregation: one warp per node ----------------
__global__ void k_agg(const float* __restrict__ x, float* __restrict__ mean,
                      const int* __restrict__ rowptr, const int* __restrict__ col,
                      const float* __restrict__ inv, int n) {
    int w = (blockIdx.x * blockDim.x + threadIdx.x) >> 5;
    int lane = threadIdx.x & 31;
    if (w >= n) return;
    int s = rowptr[w], e = rowptr[w + 1];
    const float2* base = reinterpret_cast<const float2*>(x);
    float ax = 0.f, ay = 0.f;
    int i = s;
    for (; i + 4 <= e; i += 4) {
        int s0 = __ldg(&col[i + 0]);
        int s1 = __ldg(&col[i + 1]);
        int s2 = __ldg(&col[i + 2]);
        int s3 = __ldg(&col[i + 3]);
        float2 v0 = base[(size_t)s0 * 32 + lane];
        float2 v1 = base[(size_t)s1 * 32 + lane];
        float2 v2 = base[(size_t)s2 * 32 + lane];
        float2 v3 = base[(size_t)s3 * 32 + lane];
        ax += v0.x + v1.x + v2.x + v3.x;
        ay += v0.y + v1.y + v2.y + v3.y;
    }
    for (; i < e; i++) {
        int s0 = __ldg(&col[i]);
        float2 v0 = base[(size_t)s0 * 32 + lane];
        ax += v0.x; ay += v0.y;
    }
    float iv = inv[w];
    float2 m; m.x = ax * iv; m.y = ay * iv;
    reinterpret_cast<float2*>(mean)[(size_t)w * 32 + lane] = m;
}

// ---------------- fused dual-GEMM + bias + ReLU ----------------
// hout[n][o] = relu( sum_k mean[n][k]*Wl[k][o] + sum_k hin[n][k]*Wr[k][o] + b[o] )
// Packed as f32x2: A = (mean, hin), W = (Wl, Wr); out = acc.x + acc.y + b.
#define GEMM_SMEM (2 * 64 * 64 * 8 + 256)

__global__ void __launch_bounds__(256) k_gemm(
    const float* __restrict__ mean, const float* __restrict__ hin,
    const float* __restrict__ Wl, const float* __restrict__ Wr,
    const float* __restrict__ bias, float* __restrict__ hout, int n) {
    extern __shared__ float2 smem[];
    float2* sA = smem;               // [64 nodes][64 k]
    float2* sW = smem + 64 * 64;     // [64 k][64 o]
    float*  sB = (float*)(smem + 2 * 64 * 64);

    int t = threadIdx.x;
    int node0 = blockIdx.x * 64;

    for (int idx = t; idx < 64 * 64; idx += 256)
        sW[idx] = make_float2(Wl[idx], Wr[idx]);
    if (t < 64) sB[t] = bias[t];
    for (int idx = t; idx < 64 * 64; idx += 256) {
        int nn = idx >> 6, kk = idx & 63;
        int node = node0 + nn;
        float a = 0.f, b = 0.f;
        if (node < n) {
            a = mean[(size_t)node * 64 + kk];
            b = hin[(size_t)node * 64 + kk];
        }
        sA[idx] = make_float2(a, b);
    }
    __syncthreads();

    int tn = t >> 4;  // node group 0..15 -> nodes tn, tn+16, tn+32, tn+48
    int to = t & 15;  // out group  0..15 -> outs  to, to+16, to+32, to+48

    unsigned long long acc[4][4];
    #pragma unroll
    for (int i = 0; i < 4; i++)
        #pragma unroll
        for (int j = 0; j < 4; j++) acc[i][j] = 0ULL;

    const unsigned long long* A64 = reinterpret_cast<const unsigned long long*>(sA);
    const unsigned long long* W64 = reinterpret_cast<const unsigned long long*>(sW);

    #pragma unroll 4
    for (int k = 0; k < 64; k++) {
        unsigned long long a[4], w[4];
        #pragma unroll
        for (int i = 0; i < 4; i++) a[i] = A64[(tn + 16 * i) * 64 + k];
        #pragma unroll
        for (int j = 0; j < 4; j++) w[j] = W64[k * 64 + to + 16 * j];
        #pragma unroll
        for (int i = 0; i < 4; i++)
            #pragma unroll
            for (int j = 0; j < 4; j++)
                asm("fma.rn.f32x2 %0, %1, %2, %0;"
                    : "+l"(acc[i][j]) : "l"(a[i]), "l"(w[j]));
    }

    #pragma unroll
    for (int i = 0; i < 4; i++) {
        int node = node0 + tn + 16 * i;
        if (node < n) {
            #pragma unroll
            for (int j = 0; j < 4; j++) {
                int o = to + 16 * j;
                float2 r;
                unsigned long long v = acc[i][j];
                r = *reinterpret_cast<float2*>(&v);
                float out = r.x + r.y + sB[o];
                hout[(size_t)node * 64 + o] = fmaxf(out, 0.f);
            }
        }
    }
}

// ---------------- classifier + log_softmax: one warp per node ----------------
__global__ void k_cls(const float* __restrict__ h, const float* __restrict__ Wc,
                      const float* __restrict__ bc, float* __restrict__ out, int n) {
    __shared__ float sW[640];
    __shared__ float sb[16];
    int t = threadIdx.x;
    for (int idx = t; idx < 640; idx += 256) sW[idx] = Wc[idx];
    if (t < 10) sb[t] = bc[t];
    __syncthreads();
    int w = (blockIdx.x * blockDim.x + t) >> 5;
    int lane = t & 31;
    if (w >= n) return;
    float2 hv = reinterpret_cast<const float2*>(h)[(size_t)w * 32 + lane];
    float v[10];
    #pragma unroll
    for (int c = 0; c < 10; c++) {
        float p = hv.x * sW[(2 * lane) * 10 + c] + hv.y * sW[(2 * lane + 1) * 10 + c];
        #pragma unroll
        for (int d = 16; d > 0; d >>= 1) p += __shfl_xor_sync(0xffffffffu, p, d);
        v[c] = p + sb[c];
    }
    float m = v[0];
    #pragma unroll
    for (int c = 1; c < 10; c++) m = fmaxf(m, v[c]);
    float s = 0.f;
    #pragma unroll
    for (int c = 0; c < 10; c++) s += expf(v[c] - m);
    float lse = m + logf(s);
    if (lane == 0) {
        #pragma unroll
        for (int c = 0; c < 10; c++) out[(size_t)w * 10 + c] = v[c] - lse;
    }
}

// ---------------- launch ----------------
extern "C" void kernel_launch(void* const* d_in, const int* in_sizes, int n_in,
                              void* d_out, int out_size) {
    const float* x = (const float*)d_in[0];
    const void*  ei = d_in[1];
    int n = in_sizes[0] / HID;
    int e = in_sizes[1] / 2;

    const float* Wl1 = (const float*)d_in[2];
    const float* bl1 = (const float*)d_in[3];
    const float* Wr1 = (const float*)d_in[4];
    const float* Wl2 = (const float*)d_in[5];
    const float* bl2 = (const float*)d_in[6];
    const float* Wr2 = (const float*)d_in[7];
    const float* Wl3 = (const float*)d_in[8];
    const float* bl3 = (const float*)d_in[9];
    const float* Wr3 = (const float*)d_in[10];
    const float* Wc  = (const float*)d_in[11];
    const float* bc  = (const float*)d_in[12];
    float* out = (float*)d_out;

    int *deg, *rowptr, *fill, *bsums, *col;
    float *inv, *mean, *h1, *h2;
    cudaGetSymbolAddress((void**)&deg, g_deg);
    cudaGetSymbolAddress((void**)&rowptr, g_rowptr);
    cudaGetSymbolAddress((void**)&fill, g_fill);
    cudaGetSymbolAddress((void**)&bsums, g_bsums);
    cudaGetSymbolAddress((void**)&col, g_col);
    cudaGetSymbolAddress((void**)&inv, g_inv);
    cudaGetSymbolAddress((void**)&mean, g_mean);
    cudaGetSymbolAddress((void**)&h1, g_h1);
    cudaGetSymbolAddress((void**)&h2, g_h2);

    cudaFuncSetAttribute(k_gemm, cudaFuncAttributeMaxDynamicSharedMemorySize, GEMM_SMEM);

    // CSR build
    k_detect<<<1, 32>>>((const unsigned int*)ei);
    k_zero<<<(n + 255) / 256, 256>>>(deg, n);
    k_count<<<(e + 255) / 256, 256>>>(ei, deg, e);
    int nb = (n + 1023) / 1024;
    k_scan1<<<nb, 1024>>>(deg, rowptr, bsums, n);
    k_scan2<<<1, 32>>>(bsums, nb);
    k_scan3<<<(n + 255) / 256, 256>>>(rowptr, bsums, deg, fill, inv, n, e);
    k_scatter<<<(e + 255) / 256, 256>>>(ei, fill, col, e);

    int aggBlocks = (n * 32 + 255) / 256;
    int gemmBlocks = (n + 63) / 64;

    // layer 1
    k_agg<<<aggBlocks, 256>>>(x, mean, rowptr, col, inv, n);
    k_gemm<<<gemmBlocks, 256, GEMM_SMEM>>>(mean, x, Wl1, Wr1, bl1, h1, n);
    // layer 2
    k_agg<<<aggBlocks, 256>>>(h1, mean, rowptr, col, inv, n);
    k_gemm<<<gemmBlocks, 256, GEMM_SMEM>>>(mean, h1, Wl2, Wr2, bl2, h2, n);
    // layer 3
    k_agg<<<aggBlocks, 256>>>(h2, mean, rowptr, col, inv, n);
    k_gemm<<<gemmBlocks, 256, GEMM_SMEM>>>(mean, h2, Wl3, Wr3, bl3, h1, n);
    // classifier
    k_cls<<<(n * 32 + 255) / 256, 256>>>(h1, Wc, bc, out, n);
}

// round 2
// speedup vs baseline: 1.0739x; 1.0739x over previous
#include <cuda_runtime.h>
#include <cuda_fp16.h>
#include <math.h>

#define NMAX 100000
#define EMAX 1600000
#define HID 64

// ---------------- scratch (static device globals; no allocation) ----------------
__device__ int     g_deg[NMAX];
__device__ int     g_rowptr[NMAX + 1];
__device__ int     g_fill[NMAX];
__device__ int     g_bsums[256];
__device__ float   g_inv[NMAX];
__device__ int     g_col[EMAX];
__device__ __half2 g_xh[(size_t)NMAX * 32];
__device__ __half2 g_meanh[(size_t)NMAX * 32];
__device__ __half2 g_h1h[(size_t)NMAX * 32];
__device__ __half2 g_h2h[(size_t)NMAX * 32];
__device__ int     g_is64;

// ---------------- init: zero deg + detect edge_index dtype ----------------
__global__ void k_init(int* __restrict__ deg, int n, const unsigned int* __restrict__ p) {
    int i = blockIdx.x * blockDim.x + threadIdx.x;
    if (i < n) deg[i] = 0;
    if (i == 0) {
        int ok = 1;
        #pragma unroll
        for (int j = 0; j < 64; j++)
            if (p[2 * j + 1] != 0u) ok = 0;
        g_is64 = ok;
    }
}

__device__ __forceinline__ int load_idx(const void* base, long long i, int is64) {
    if (is64) return (int)((const long long*)base)[i];
    return ((const int*)base)[i];
}

// ---------------- CSR build ----------------
__global__ void k_count(const void* __restrict__ ei, int* __restrict__ deg, int e) {
    int i = blockIdx.x * blockDim.x + threadIdx.x;
    int is64 = g_is64;
    if (i < e) {
        int d = load_idx(ei, (long long)e + i, is64);
        atomicAdd(&deg[d], 1);
    }
}

__global__ void k_scan1(const int* __restrict__ deg, int* __restrict__ rowptr,
                        int* __restrict__ bsums, int n) {
    __shared__ int warp_tot[32];
    int i = blockIdx.x * 1024 + threadIdx.x;
    int lane = threadIdx.x & 31, wid = threadIdx.x >> 5;
    int v = (i < n) ? deg[i] : 0;
    int x = v;
    #pragma unroll
    for (int d = 1; d < 32; d <<= 1) {
        int y = __shfl_up_sync(0xffffffffu, x, d);
        if (lane >= d) x += y;
    }
    if (lane == 31) warp_tot[wid] = x;
    __syncthreads();
    if (wid == 0) {
        int t = warp_tot[lane];
        #pragma unroll
        for (int d = 1; d < 32; d <<= 1) {
            int y = __shfl_up_sync(0xffffffffu, t, d);
            if (lane >= d) t += y;
        }
        warp_tot[lane] = t;
    }
    __syncthreads();
    int base = (wid > 0) ? warp_tot[wid - 1] : 0;
    if (i < n) rowptr[i] = base + x - v;
    if (threadIdx.x == 0) bsums[blockIdx.x] = warp_tot[31];
}

__global__ void k_scan2(int* __restrict__ bsums, int nb) {
    if (threadIdx.x == 0 && blockIdx.x == 0) {
        int acc = 0;
        for (int b = 0; b < nb; b++) { int t = bsums[b]; bsums[b] = acc; acc += t; }
    }
}

__global__ void k_scan3(int* __restrict__ rowptr, const int* __restrict__ bsums,
                        const int* __restrict__ deg, int* __restrict__ fill,
                        float* __restrict__ inv, int n, int e) {
    int i = blockIdx.x * blockDim.x + threadIdx.x;
    if (i < n) {
        int rp = rowptr[i] + bsums[i >> 10];
        rowptr[i] = rp;
        fill[i] = rp;
        int d = deg[i];
        inv[i] = 1.0f / (float)max(d, 1);
    }
    if (i == 0) rowptr[n] = e;
}

__global__ void k_scatter(const void* __restrict__ ei, int* __restrict__ fill,
                          int* __restrict__ col, int e) {
    int i = blockIdx.x * blockDim.x + threadIdx.x;
    int is64 = g_is64;
    if (i < e) {
        int d = load_idx(ei, (long long)e + i, is64);
        int s = load_idx(ei, (long long)i, is64);
        int p = atomicAdd(&fill[d], 1);
        col[p] = s;
    }
}

// ---------------- convert x (fp32) -> half2 ----------------
__global__ void k_cvt(const float2* __restrict__ x, __half2* __restrict__ xh, int n32) {
    int i = blockIdx.x * blockDim.x + threadIdx.x;
    if (i < n32) {
        float2 v = x[i];
        xh[i] = __floats2half2_rn(v.x, v.y);
    }
}

// ---------------- mean aggregation: one warp per node, half2 gather ----------------
__global__ void k_agg(const __half2* __restrict__ x, __half2* __restrict__ mean,
                      const int* __restrict__ rowptr, const int* __restrict__ col,
                      const float* __restrict__ inv, int n) {
    int w = (blockIdx.x * blockDim.x + threadIdx.x) >> 5;
    int lane = threadIdx.x & 31;
    if (w >= n) return;
    int s = rowptr[w], e = rowptr[w + 1];
    float ax = 0.f, ay = 0.f;
    int i = s;
    for (; i + 4 <= e; i += 4) {
        int s0 = __ldg(&col[i + 0]);
        int s1 = __ldg(&col[i + 1]);
        int s2 = __ldg(&col[i + 2]);
        int s3 = __ldg(&col[i + 3]);
        __half2 h0 = x[(size_t)s0 * 32 + lane];
        __half2 h1 = x[(size_t)s1 * 32 + lane];
        __half2 h2 = x[(size_t)s2 * 32 + lane];
        __half2 h3 = x[(size_t)s3 * 32 + lane];
        float2 v0 = __half22float2(h0);
        float2 v1 = __half22float2(h1);
        float2 v2 = __half22float2(h2);
        float2 v3 = __half22float2(h3);
        ax += (v0.x + v1.x) + (v2.x + v3.x);
        ay += (v0.y + v1.y) + (v2.y + v3.y);
    }
    for (; i < e; i++) {
        int s0 = __ldg(&col[i]);
        float2 v0 = __half22float2(x[(size_t)s0 * 32 + lane]);
        ax += v0.x; ay += v0.y;
    }
    float iv = inv[w];
    mean[(size_t)w * 32 + lane] = __floats2half2_rn(ax * iv, ay * iv);
}

// ---------------- fused dual-GEMM + bias + ReLU (f32x2 packed FFMA) ----------------
// hout[n][o] = relu( sum_k mean[n][k]*Wl[k][o] + sum_k hin[n][k]*Wr[k][o] + b[o] )
#define GEMM_SMEM (2 * 64 * 64 * 8 + 256)

__global__ void __launch_bounds__(256) k_gemm(
    const __half2* __restrict__ meanh, const __half2* __restrict__ hinh,
    const float* __restrict__ Wl, const float* __restrict__ Wr,
    const float* __restrict__ bias, __half2* __restrict__ houth, int n) {
    extern __shared__ float2 smem[];
    float2* sA = smem;               // [64 nodes][64 k] packed (mean, hin)
    float2* sW = smem + 64 * 64;     // [64 k][64 o]   packed (Wl, Wr)
    float*  sB = (float*)(smem + 2 * 64 * 64);

    int t = threadIdx.x;
    int node0 = blockIdx.x * 64;

    for (int idx = t; idx < 64 * 64; idx += 256)
        sW[idx] = make_float2(Wl[idx], Wr[idx]);
    if (t < 64) sB[t] = bias[t];
    for (int idx2 = t; idx2 < 64 * 32; idx2 += 256) {
        int nn = idx2 >> 5, kk2 = idx2 & 31;
        int node = node0 + nn;
        float2 mf = make_float2(0.f, 0.f), hf = make_float2(0.f, 0.f);
        if (node < n) {
            mf = __half22float2(meanh[(size_t)node * 32 + kk2]);
            hf = __half22float2(hinh[(size_t)node * 32 + kk2]);
        }
        sA[nn * 64 + 2 * kk2 + 0] = make_float2(mf.x, hf.x);
        sA[nn * 64 + 2 * kk2 + 1] = make_float2(mf.y, hf.y);
    }
    __syncthreads();

    int tn = t >> 4;  // node group: nodes tn, tn+16, tn+32, tn+48
    int to = t & 15;  // out group:  outs  to, to+16, to+32, to+48

    unsigned long long acc[4][4];
    #pragma unroll
    for (int i = 0; i < 4; i++)
        #pragma unroll
        for (int j = 0; j < 4; j++) acc[i][j] = 0ULL;

    const unsigned long long* A64 = reinterpret_cast<const unsigned long long*>(sA);
    const unsigned long long* W64 = reinterpret_cast<const unsigned long long*>(sW);

    #pragma unroll 4
    for (int k = 0; k < 64; k++) {
        unsigned long long a[4], w[4];
        #pragma unroll
        for (int i = 0; i < 4; i++) a[i] = A64[(tn + 16 * i) * 64 + k];
        #pragma unroll
        for (int j = 0; j < 4; j++) w[j] = W64[k * 64 + to + 16 * j];
        #pragma unroll
        for (int i = 0; i < 4; i++)
            #pragma unroll
            for (int j = 0; j < 4; j++)
                asm("fma.rn.f32x2 %0, %1, %2, %0;"
                    : "+l"(acc[i][j]) : "l"(a[i]), "l"(w[j]));
    }
    __syncthreads();

    // stage half outputs in smem (reuse sW region), then coalesced 16B writes
    __half* sH = (__half*)sW;   // [64 nodes][64 o] halves = 8KB
    #pragma unroll
    for (int i = 0; i < 4; i++) {
        #pragma unroll
        for (int j = 0; j < 4; j++) {
            int o = to + 16 * j;
            unsigned long long v = acc[i][j];
            float2 r = *reinterpret_cast<float2*>(&v);
            float out = fmaxf(r.x + r.y + sB[o], 0.f);
            sH[(tn + 16 * i) * 64 + o] = __float2half_rn(out);
        }
    }
    __syncthreads();

    const int4* src = reinterpret_cast<const int4*>(sH);
    int4* dst = reinterpret_cast<int4*>(houth + (size_t)node0 * 32);
    for (int idx = t; idx < 512; idx += 256) {     // 512 x 16B = 8KB
        int node = node0 + (idx >> 3);
        if (node < n) dst[idx] = src[idx];
    }
}

// ---------------- classifier + log_softmax: one warp per node ----------------
__global__ void k_cls(const __half2* __restrict__ h, const float* __restrict__ Wc,
                      const float* __restrict__ bc, float* __restrict__ out, int n) {
    __shared__ float sW[640];
    __shared__ float sb[16];
    int t = threadIdx.x;
    for (int idx = t; idx < 640; idx += 256) sW[idx] = Wc[idx];
    if (t < 10) sb[t] = bc[t];
    __syncthreads();
    int w = (blockIdx.x * blockDim.x + t) >> 5;
    int lane = t & 31;
    if (w >= n) return;
    float2 hv = __half22float2(h[(size_t)w * 32 + lane]);
    float v[10];
    #pragma unroll
    for (int c = 0; c < 10; c++) {
        float p = hv.x * sW[(2 * lane) * 10 + c] + hv.y * sW[(2 * lane + 1) * 10 + c];
        #pragma unroll
        for (int d = 16; d > 0; d >>= 1) p += __shfl_xor_sync(0xffffffffu, p, d);
        v[c] = p + sb[c];
    }
    float m = v[0];
    #pragma unroll
    for (int c = 1; c < 10; c++) m = fmaxf(m, v[c]);
    float s = 0.f;
    #pragma unroll
    for (int c = 0; c < 10; c++) s += expf(v[c] - m);
    float lse = m + logf(s);
    if (lane == 0) {
        #pragma unroll
        for (int c = 0; c < 10; c++) out[(size_t)w * 10 + c] = v[c] - lse;
    }
}

// ---------------- launch ----------------
extern "C" void kernel_launch(void* const* d_in, const int* in_sizes, int n_in,
                              void* d_out, int out_size) {
    const float* x = (const float*)d_in[0];
    const void*  ei = d_in[1];
    int n = in_sizes[0] / HID;
    int e = in_sizes[1] / 2;

    const float* Wl1 = (const float*)d_in[2];
    const float* bl1 = (const float*)d_in[3];
    const float* Wr1 = (const float*)d_in[4];
    const float* Wl2 = (const float*)d_in[5];
    const float* bl2 = (const float*)d_in[6];
    const float* Wr2 = (const float*)d_in[7];
    const float* Wl3 = (const float*)d_in[8];
    const float* bl3 = (const float*)d_in[9];
    const float* Wr3 = (const float*)d_in[10];
    const float* Wc  = (const float*)d_in[11];
    const float* bc  = (const float*)d_in[12];
    float* out = (float*)d_out;

    int *deg, *rowptr, *fill, *bsums, *col;
    float *inv;
    __half2 *xh, *meanh, *h1h, *h2h;
    cudaGetSymbolAddress((void**)&deg, g_deg);
    cudaGetSymbolAddress((void**)&rowptr, g_rowptr);
    cudaGetSymbolAddress((void**)&fill, g_fill);
    cudaGetSymbolAddress((void**)&bsums, g_bsums);
    cudaGetSymbolAddress((void**)&col, g_col);
    cudaGetSymbolAddress((void**)&inv, g_inv);
    cudaGetSymbolAddress((void**)&xh, g_xh);
    cudaGetSymbolAddress((void**)&meanh, g_meanh);
    cudaGetSymbolAddress((void**)&h1h, g_h1h);
    cudaGetSymbolAddress((void**)&h2h, g_h2h);

    cudaFuncSetAttribute(k_gemm, cudaFuncAttributeMaxDynamicSharedMemorySize, GEMM_SMEM);

    // CSR build + fp16 conversion of x
    k_init<<<(n + 255) / 256, 256>>>(deg, n, (const unsigned int*)ei);
    k_count<<<(e + 255) / 256, 256>>>(ei, deg, e);
    int nb = (n + 1023) / 1024;
    k_scan1<<<nb, 1024>>>(deg, rowptr, bsums, n);
    k_scan2<<<1, 32>>>(bsums, nb);
    k_scan3<<<(n + 255) / 256, 256>>>(rowptr, bsums, deg, fill, inv, n, e);
    k_scatter<<<(e + 255) / 256, 256>>>(ei, fill, col, e);
    k_cvt<<<(n * 32 + 255) / 256, 256>>>((const float2*)x, xh, n * 32);

    int aggBlocks = (n * 32 + 255) / 256;
    int gemmBlocks = (n + 63) / 64;

    // layer 1
    k_agg<<<aggBlocks, 256>>>(xh, meanh, rowptr, col, inv, n);
    k_gemm<<<gemmBlocks, 256, GEMM_SMEM>>>(meanh, xh, Wl1, Wr1, bl1, h1h, n);
    // layer 2
    k_agg<<<aggBlocks, 256>>>(h1h, meanh, rowptr, col, inv, n);
    k_gemm<<<gemmBlocks, 256, GEMM_SMEM>>>(meanh, h1h, Wl2, Wr2, bl2, h2h, n);
    // layer 3
    k_agg<<<aggBlocks, 256>>>(h2h, meanh, rowptr, col, inv, n);
    k_gemm<<<gemmBlocks, 256, GEMM_SMEM>>>(meanh, h2h, Wl3, Wr3, bl3, h1h, n);
    // classifier
    k_cls<<<(n * 32 + 255) / 256, 256>>>(h1h, Wc, bc, out, n);
}